// round 12
// baseline (speedup 1.0000x reference)
#include <cuda_runtime.h>
#include <cuda_fp16.h>
#include <cuda_bf16.h>
#include <cstdint>

// MaxAggregator: out[n, :] = max over s of features[neighbor_idx[n, s], :]
// N = 100000 nodes, S = 10 samples, D = 256 features (fp32).
//
// R12: hide the fp16-convert tax via column-halving + fused overlap.
//   K1: convert half0 (cols 0..127) to fp16            (~9us, DRAM-read)
//   K2: FUSED: 1/3 of blocks convert half1, 2/3 gather half0
//       (DRAM-bound convert overlaps L2-bound gather)
//   K3: gather half1
// Each 25.6MB half-table is L2-retainable against the write stream.
// fp16 rounding: rel_err ~2.1e-4 (measured), under the 1e-3 gate.

#define NUM_SAMPLE 10
#define D_FEAT 256
#define N_NODES_MAX 100000
#define HALF_COLS 128
#define HALF_ROW_BYTES (HALF_COLS * 2)     // 256 B fp16 half-row
#define ROW_BYTES_F32 (D_FEAT * 4)         // 1024

// Two fp16 half-tables, 25.6 MB each.
__device__ uint4 g_half0[(size_t)N_NODES_MAX * 16];
__device__ uint4 g_half1[(size_t)N_NODES_MAX * 16];

__device__ __forceinline__ uint32_t h2_bits(__half2 h) {
    union { __half2 h; uint32_t u; } c; c.h = h; return c.u;
}
__device__ __forceinline__ __half2 bits_h2(uint32_t u) {
    union { uint32_t u; __half2 h; } c; c.u = u; return c.h;
}

// Convert element i (of n_nodes*16) of half h: 2x float4 -> 1x uint4.
__device__ __forceinline__ void do_convert(
    const float4* __restrict__ src, uint4* __restrict__ dst, int h, int i)
{
    int node = i >> 4;
    int p    = i & 15;                      // pair index within half-row
    const float4* rp = src + node * (D_FEAT / 4) + h * (HALF_COLS / 4) + p * 2;
    float4 a = __ldg(rp);
    float4 b = __ldg(rp + 1);
    uint4 packed;
    packed.x = h2_bits(__floats2half2_rn(a.x, a.y));
    packed.y = h2_bits(__floats2half2_rn(a.z, a.w));
    packed.z = h2_bits(__floats2half2_rn(b.x, b.y));
    packed.w = h2_bits(__floats2half2_rn(b.z, b.w));
    dst[i] = packed;
}

// Gather half h for gather-block gb: warp-per-node, lane owns 8B of the
// 256B half-row (cols [4*lane, 4*lane+4)).
__device__ __forceinline__ void do_gather(
    const int* __restrict__ neighbor_idx, const uint4* __restrict__ tblv,
    float* __restrict__ out, int n_nodes, int h, int gb)
{
    int wid  = threadIdx.x >> 5;
    int lane = threadIdx.x & 31;
    int node = gb * 8 + wid;
    if (node >= n_nodes) return;

    int my = 0;
    if (lane < NUM_SAMPLE) my = __ldg(neighbor_idx + node * NUM_SAMPLE + lane);
    int s0 = __shfl_sync(0xffffffffu, my, 0);
    int s1 = __shfl_sync(0xffffffffu, my, 1);
    int s2 = __shfl_sync(0xffffffffu, my, 2);
    int s3 = __shfl_sync(0xffffffffu, my, 3);
    int s4 = __shfl_sync(0xffffffffu, my, 4);
    int s5 = __shfl_sync(0xffffffffu, my, 5);
    int s6 = __shfl_sync(0xffffffffu, my, 6);
    int s7 = __shfl_sync(0xffffffffu, my, 7);
    int s8 = __shfl_sync(0xffffffffu, my, 8);
    int s9 = __shfl_sync(0xffffffffu, my, 9);

    const char* tbl = (const char*)tblv;
    uint32_t loff = (uint32_t)lane * 8u;

    uint2 v0 = *(const uint2*)(tbl + ((uint32_t)s0 * HALF_ROW_BYTES + loff));
    uint2 v1 = *(const uint2*)(tbl + ((uint32_t)s1 * HALF_ROW_BYTES + loff));
    uint2 v2 = *(const uint2*)(tbl + ((uint32_t)s2 * HALF_ROW_BYTES + loff));
    uint2 v3 = *(const uint2*)(tbl + ((uint32_t)s3 * HALF_ROW_BYTES + loff));
    uint2 v4 = *(const uint2*)(tbl + ((uint32_t)s4 * HALF_ROW_BYTES + loff));
    uint2 v5 = *(const uint2*)(tbl + ((uint32_t)s5 * HALF_ROW_BYTES + loff));
    uint2 v6 = *(const uint2*)(tbl + ((uint32_t)s6 * HALF_ROW_BYTES + loff));
    uint2 v7 = *(const uint2*)(tbl + ((uint32_t)s7 * HALF_ROW_BYTES + loff));
    uint2 v8 = *(const uint2*)(tbl + ((uint32_t)s8 * HALF_ROW_BYTES + loff));
    uint2 v9 = *(const uint2*)(tbl + ((uint32_t)s9 * HALF_ROW_BYTES + loff));

    __half2 m0 = __hmax2(__hmax2(__hmax2(bits_h2(v0.x), bits_h2(v1.x)),
                                 __hmax2(bits_h2(v2.x), bits_h2(v3.x))),
                         __hmax2(__hmax2(bits_h2(v4.x), bits_h2(v5.x)),
                                 __hmax2(bits_h2(v6.x), bits_h2(v7.x))));
    m0 = __hmax2(m0, __hmax2(bits_h2(v8.x), bits_h2(v9.x)));
    __half2 m1 = __hmax2(__hmax2(__hmax2(bits_h2(v0.y), bits_h2(v1.y)),
                                 __hmax2(bits_h2(v2.y), bits_h2(v3.y))),
                         __hmax2(__hmax2(bits_h2(v4.y), bits_h2(v5.y)),
                                 __hmax2(bits_h2(v6.y), bits_h2(v7.y))));
    m1 = __hmax2(m1, __hmax2(bits_h2(v8.y), bits_h2(v9.y)));

    float2 f0 = __half22float2(m0);
    float2 f1 = __half22float2(m1);
    *(float4*)((char*)out + ((uint32_t)node * ROW_BYTES_F32 +
                             (uint32_t)h * (HALF_COLS * 4) +
                             (uint32_t)lane * 16u)) =
        make_float4(f0.x, f0.y, f1.x, f1.y);
}

// ---- K1: convert half 0 ----
__global__ void __launch_bounds__(256) convert0_kernel(
    const float4* __restrict__ src, int n_nodes)
{
    int i = blockIdx.x * blockDim.x + threadIdx.x;
    if (i < n_nodes * 16) do_convert(src, g_half0, 0, i);
}

// ---- K2: fused convert half1 (1/3 of blocks) + gather half0 (2/3) ----
__global__ void __launch_bounds__(256) fused_kernel(
    const float4* __restrict__ src, const int* __restrict__ neighbor_idx,
    float* __restrict__ out, int n_nodes)
{
    int bid = blockIdx.x;
    int r = bid % 3;
    if (r == 2) {
        int cb = bid / 3;
        int i = cb * 256 + threadIdx.x;
        if (i < n_nodes * 16) do_convert(src, g_half1, 1, i);
    } else {
        int gb = (bid / 3) * 2 + r;
        do_gather(neighbor_idx, g_half0, out, n_nodes, 0, gb);
    }
}

// ---- K3: gather half 1 ----
__global__ void __launch_bounds__(256) gather1_kernel(
    const int* __restrict__ neighbor_idx, float* __restrict__ out, int n_nodes)
{
    do_gather(neighbor_idx, g_half1, out, n_nodes, 1, blockIdx.x);
}

extern "C" void kernel_launch(void* const* d_in, const int* in_sizes, int n_in,
                              void* d_out, int out_size) {
    const int* neighbor_idx = (const int*)d_in[0];       // [N, 10] int32
    const float* features   = (const float*)d_in[1];     // [U, 256] fp32
    float* out = (float*)d_out;

    int n_nodes = in_sizes[0] / NUM_SAMPLE;              // 100000

    int cgrid = (n_nodes * 16 + 255) / 256;              // 6250 convert blocks
    int ggrid = (n_nodes + 7) / 8;                       // 12500 gather blocks

    convert0_kernel<<<cgrid, 256>>>((const float4*)features, n_nodes);
    fused_kernel<<<cgrid + ggrid, 256>>>((const float4*)features,
                                         neighbor_idx, out, n_nodes);
    gather1_kernel<<<ggrid, 256>>>(neighbor_idx, out, n_nodes);
}

// round 13
// speedup vs baseline: 1.0284x; 1.0284x over previous
#include <cuda_runtime.h>
#include <cuda_fp16.h>
#include <cuda_bf16.h>
#include <cstdint>

// MaxAggregator: out[n, :] = max over s of features[neighbor_idx[n, s], :]
// N = 100000 nodes, S = 10 samples, D = 256 features (fp32).
//
// R13: R11 two-kernel structure, per-kernel limiters attacked:
//  Convert: 4x float4 loads + 2x uint4 stores per thread (MLP=4/thread,
//           was 2) -> push DRAM-read toward the ~17us floor.
//  Gather:  warp-per-node fp16, ALL 10 uint4 loads issued before the
//           reduction (in-flight loads/SM ~400 vs ~255 with 5+5 batching;
//           trades occ 80%->~62% for +57% latency hiding; stalls are
//           long-scoreboard, not issue).

#define NUM_SAMPLE 10
#define D_FEAT 256
#define N_NODES_MAX 100000
#define ROW_BYTES_F16 (D_FEAT * 2)      // 512
#define ROW_BYTES_F32 (D_FEAT * 4)      // 1024

__device__ __half2 g_feat16[(size_t)N_NODES_MAX * D_FEAT / 2];  // 51.2 MB

__device__ __forceinline__ uint32_t h2_bits(__half2 h) {
    union { __half2 h; uint32_t u; } c; c.h = h; return c.u;
}
__device__ __forceinline__ __half2 bits_h2(uint32_t u) {
    union { uint32_t u; __half2 h; } c; c.u = u; return c.h;
}

// ---------------- Kernel 1: fp32 -> fp16 table conversion ----------------
// Each thread: 4x float4 loads (64B), 2x uint4 stores (32B). MLP=4.
__global__ void __launch_bounds__(256) convert_kernel(
    const float4* __restrict__ src, int n_quads)   // n_quads = total_f4 / 4
{
    int i = blockIdx.x * blockDim.x + threadIdx.x;
    if (i >= n_quads) return;
    float4 a = __ldg(src + 4 * i);
    float4 b = __ldg(src + 4 * i + 1);
    float4 c = __ldg(src + 4 * i + 2);
    float4 d = __ldg(src + 4 * i + 3);
    uint4 p0, p1;
    p0.x = h2_bits(__floats2half2_rn(a.x, a.y));
    p0.y = h2_bits(__floats2half2_rn(a.z, a.w));
    p0.z = h2_bits(__floats2half2_rn(b.x, b.y));
    p0.w = h2_bits(__floats2half2_rn(b.z, b.w));
    p1.x = h2_bits(__floats2half2_rn(c.x, c.y));
    p1.y = h2_bits(__floats2half2_rn(c.z, c.w));
    p1.z = h2_bits(__floats2half2_rn(d.x, d.y));
    p1.w = h2_bits(__floats2half2_rn(d.z, d.w));
    ((uint4*)g_feat16)[2 * i]     = p0;
    ((uint4*)g_feat16)[2 * i + 1] = p1;
}

// ---------------- Kernel 2: warp-per-node fp16 gather + hmax2 -------------
__global__ void __launch_bounds__(256) max_agg_kernel(
    const int* __restrict__ neighbor_idx,   // [N, 10]
    float* __restrict__ out,                // [N, 256]
    int n_nodes)
{
    int wid  = threadIdx.x >> 5;            // warp in block (0..7)
    int lane = threadIdx.x & 31;
    int node = blockIdx.x * 8 + wid;
    if (node >= n_nodes) return;

    // Load the 10 indices with 10 lanes, broadcast via shuffle.
    int my = 0;
    if (lane < NUM_SAMPLE) my = __ldg(neighbor_idx + node * NUM_SAMPLE + lane);
    int s0 = __shfl_sync(0xffffffffu, my, 0);
    int s1 = __shfl_sync(0xffffffffu, my, 1);
    int s2 = __shfl_sync(0xffffffffu, my, 2);
    int s3 = __shfl_sync(0xffffffffu, my, 3);
    int s4 = __shfl_sync(0xffffffffu, my, 4);
    int s5 = __shfl_sync(0xffffffffu, my, 5);
    int s6 = __shfl_sync(0xffffffffu, my, 6);
    int s7 = __shfl_sync(0xffffffffu, my, 7);
    int s8 = __shfl_sync(0xffffffffu, my, 8);
    int s9 = __shfl_sync(0xffffffffu, my, 9);

    // Lane covers 16B (8 halves) of each 512B row.
    const char* tbl = (const char*)g_feat16;
    uint32_t loff = (uint32_t)lane * 16u;

    // ALL 10 loads issued back-to-back: MLP=10 per warp.
    uint4 v0 = *(const uint4*)(tbl + ((uint32_t)s0 * ROW_BYTES_F16 + loff));
    uint4 v1 = *(const uint4*)(tbl + ((uint32_t)s1 * ROW_BYTES_F16 + loff));
    uint4 v2 = *(const uint4*)(tbl + ((uint32_t)s2 * ROW_BYTES_F16 + loff));
    uint4 v3 = *(const uint4*)(tbl + ((uint32_t)s3 * ROW_BYTES_F16 + loff));
    uint4 v4 = *(const uint4*)(tbl + ((uint32_t)s4 * ROW_BYTES_F16 + loff));
    uint4 v5 = *(const uint4*)(tbl + ((uint32_t)s5 * ROW_BYTES_F16 + loff));
    uint4 v6 = *(const uint4*)(tbl + ((uint32_t)s6 * ROW_BYTES_F16 + loff));
    uint4 v7 = *(const uint4*)(tbl + ((uint32_t)s7 * ROW_BYTES_F16 + loff));
    uint4 v8 = *(const uint4*)(tbl + ((uint32_t)s8 * ROW_BYTES_F16 + loff));
    uint4 v9 = *(const uint4*)(tbl + ((uint32_t)s9 * ROW_BYTES_F16 + loff));

    // Reduce in arrival order (consume early loads first).
    __half2 m0 = __hmax2(bits_h2(v0.x), bits_h2(v1.x));
    __half2 m1 = __hmax2(bits_h2(v0.y), bits_h2(v1.y));
    __half2 m2 = __hmax2(bits_h2(v0.z), bits_h2(v1.z));
    __half2 m3 = __hmax2(bits_h2(v0.w), bits_h2(v1.w));
    m0 = __hmax2(m0, __hmax2(bits_h2(v2.x), bits_h2(v3.x)));
    m1 = __hmax2(m1, __hmax2(bits_h2(v2.y), bits_h2(v3.y)));
    m2 = __hmax2(m2, __hmax2(bits_h2(v2.z), bits_h2(v3.z)));
    m3 = __hmax2(m3, __hmax2(bits_h2(v2.w), bits_h2(v3.w)));
    m0 = __hmax2(m0, __hmax2(bits_h2(v4.x), bits_h2(v5.x)));
    m1 = __hmax2(m1, __hmax2(bits_h2(v4.y), bits_h2(v5.y)));
    m2 = __hmax2(m2, __hmax2(bits_h2(v4.z), bits_h2(v5.z)));
    m3 = __hmax2(m3, __hmax2(bits_h2(v4.w), bits_h2(v5.w)));
    m0 = __hmax2(m0, __hmax2(bits_h2(v6.x), bits_h2(v7.x)));
    m1 = __hmax2(m1, __hmax2(bits_h2(v6.y), bits_h2(v7.y)));
    m2 = __hmax2(m2, __hmax2(bits_h2(v6.z), bits_h2(v7.z)));
    m3 = __hmax2(m3, __hmax2(bits_h2(v6.w), bits_h2(v7.w)));
    m0 = __hmax2(m0, __hmax2(bits_h2(v8.x), bits_h2(v9.x)));
    m1 = __hmax2(m1, __hmax2(bits_h2(v8.y), bits_h2(v9.y)));
    m2 = __hmax2(m2, __hmax2(bits_h2(v8.z), bits_h2(v9.z)));
    m3 = __hmax2(m3, __hmax2(bits_h2(v8.w), bits_h2(v9.w)));

    // Widen to fp32 and store 8 floats (32B) per lane.
    float2 f0 = __half22float2(m0);
    float2 f1 = __half22float2(m1);
    float2 f2 = __half22float2(m2);
    float2 f3 = __half22float2(m3);

    char* obase = (char*)out + ((uint32_t)node * ROW_BYTES_F32 + (uint32_t)lane * 32u);
    *(float4*)(obase)      = make_float4(f0.x, f0.y, f1.x, f1.y);
    *(float4*)(obase + 16) = make_float4(f2.x, f2.y, f3.x, f3.y);
}

extern "C" void kernel_launch(void* const* d_in, const int* in_sizes, int n_in,
                              void* d_out, int out_size) {
    const int* neighbor_idx = (const int*)d_in[0];       // [N, 10] int32
    const float* features   = (const float*)d_in[1];     // [U, 256] fp32
    float* out = (float*)d_out;

    int n_nodes = in_sizes[0] / NUM_SAMPLE;              // 100000
    int n_quads = in_sizes[1] / 16;                      // 1.6M (4 float4 each)

    // Kernel 1: convert table to fp16 (51.2 MB).
    int cblock = 256;
    int cgrid = (n_quads + cblock - 1) / cblock;         // 6250
    convert_kernel<<<cgrid, cblock>>>((const float4*)features, n_quads);

    // Kernel 2: warp-per-node gather + max.
    int gblock = 256;                                    // 8 warps = 8 nodes
    int ggrid = (n_nodes + 7) / 8;                       // 12500
    max_agg_kernel<<<ggrid, gblock>>>(neighbor_idx, out, n_nodes);
}